// round 2
// baseline (speedup 1.0000x reference)
#include <cuda_runtime.h>
#include <cstdint>

// Problem constants (fixed shapes for this problem instance)
#define IN_SIZE   128
#define E_SIZE    32
#define H_SIZE    128
#define K_TOT     160            // IN_SIZE + E_SIZE
#define THRESH    0.5f

#define N_MAX     50000
#define E_MAX     1600000

// ---------------- device scratch (static, allocation-free) ----------------
__device__ int   g_cnt[N_MAX];
__device__ int   g_offs[N_MAX + 1];
__device__ int   g_cur[N_MAX];
__device__ int   g_eidx[E_MAX];
__device__ float g_agg[(size_t)N_MAX * E_SIZE];

// ---------------- K0: zero histogram ----------------
__global__ void k_zero(int N) {
    int i = blockIdx.x * blockDim.x + threadIdx.x;
    if (i < N) g_cnt[i] = 0;
}

// ---------------- K1: degree histogram ----------------
__global__ void k_hist(const int* __restrict__ dst, int E) {
    int i = blockIdx.x * blockDim.x + threadIdx.x;
    if (i < E) atomicAdd(&g_cnt[dst[i]], 1);
}

// ---------------- K2: single-block exclusive scan over g_cnt -> g_offs, g_cur ----------------
__global__ void k_scan(int N) {
    __shared__ int s[1024];
    int t = threadIdx.x;
    int chunk = (N + 1023) / 1024;
    int lo = t * chunk;
    int hi = lo + chunk; if (hi > N) hi = N; if (lo > N) lo = N;

    int sum = 0;
    for (int i = lo; i < hi; ++i) sum += g_cnt[i];
    s[t] = sum;
    __syncthreads();
    // Hillis-Steele inclusive scan (read phase and write phase fully separated)
    for (int d = 1; d < 1024; d <<= 1) {
        int v = (t >= d) ? s[t - d] : 0;
        __syncthreads();
        if (t >= d) s[t] += v;
        __syncthreads();
    }
    int base = (t == 0) ? 0 : s[t - 1];
    for (int i = lo; i < hi; ++i) {
        g_offs[i] = base;
        g_cur[i]  = base;
        base += g_cnt[i];
    }
    if (t == 1023) g_offs[N] = base;   // == E
}

// ---------------- K3: scatter edge indices into CSR ----------------
__global__ void k_scatter(const int* __restrict__ dst, int E) {
    int i = blockIdx.x * blockDim.x + threadIdx.x;
    if (i < E) {
        int d = dst[i];
        int p = atomicAdd(&g_cur[d], 1);
        g_eidx[p] = i;
    }
}

// ---------------- K4: per-node gather pass (warp per node) ----------------
// Pass A: esum -> hk, ||hk||^2. Pass B: cosine filter + masked mean. Writes g_agg.
__global__ void k_nodepass(const float* __restrict__ ef, int N) {
    int warp = (blockIdx.x * blockDim.x + threadIdx.x) >> 5;
    if (warp >= N) return;
    int lane = threadIdx.x & 31;

    int start = __ldg(&g_offs[warp]);
    int end   = __ldg(&g_offs[warp + 1]);
    int deg   = end - start;

    float esum = 0.f;
#pragma unroll 4
    for (int i = start; i < end; ++i) {
        int e = __ldg(&g_eidx[i]);
        esum += __ldg(&ef[(size_t)e * E_SIZE + lane]);
    }
    float hk = (deg > 0) ? (esum / (float)deg) : 0.f;

    float nh = hk * hk;
#pragma unroll
    for (int o = 16; o; o >>= 1) nh += __shfl_xor_sync(0xffffffffu, nh, o);

    float ssum = 0.f;
    float scnt = 0.f;
    int i = start;
    // unroll-by-2: two independent shuffle-reduction chains in flight
    for (; i + 1 < end; i += 2) {
        int e0 = __ldg(&g_eidx[i]);
        int e1 = __ldg(&g_eidx[i + 1]);
        float v0 = __ldg(&ef[(size_t)e0 * E_SIZE + lane]);
        float v1 = __ldg(&ef[(size_t)e1 * E_SIZE + lane]);
        float d0 = hk * v0, q0 = v0 * v0;
        float d1 = hk * v1, q1 = v1 * v1;
#pragma unroll
        for (int o = 16; o; o >>= 1) {
            d0 += __shfl_xor_sync(0xffffffffu, d0, o);
            q0 += __shfl_xor_sync(0xffffffffu, q0, o);
            d1 += __shfl_xor_sync(0xffffffffu, d1, o);
            q1 += __shfl_xor_sync(0xffffffffu, q1, o);
        }
        float c0 = d0 / sqrtf(nh * q0);   // NaN when den==0 -> excluded (matches ref)
        float c1 = d1 / sqrtf(nh * q1);
        if (c0 < THRESH) { ssum += v0; scnt += 1.f; }
        if (c1 < THRESH) { ssum += v1; scnt += 1.f; }
    }
    if (i < end) {
        int e0 = __ldg(&g_eidx[i]);
        float v0 = __ldg(&ef[(size_t)e0 * E_SIZE + lane]);
        float d0 = hk * v0, q0 = v0 * v0;
#pragma unroll
        for (int o = 16; o; o >>= 1) {
            d0 += __shfl_xor_sync(0xffffffffu, d0, o);
            q0 += __shfl_xor_sync(0xffffffffu, q0, o);
        }
        float c0 = d0 / sqrtf(nh * q0);
        if (c0 < THRESH) { ssum += v0; scnt += 1.f; }
    }

    float agg = (scnt > 0.f) ? (ssum / scnt) : hk;
    g_agg[(size_t)warp * E_SIZE + lane] = agg;
}

// ---------------- K5: GEMM out[n][h] = sum_k x[n][k] * W[h][k], x = [h_in | agg] ----------------
// Packed-fp32 (fma.rn.f32x2): W pre-packed as output pairs in smem; 16-node tile.
// blockDim = 256: thread t -> pair p = t&63 (outputs 2p,2p+1), sel = t>>6 -> 4 nodes of the tile.
#define GEMM_NB 16
#define SMEM_W_BYTES (K_TOT * 64 * sizeof(float2))              // 81920
#define SMEM_X_BYTES (GEMM_NB * K_TOT * sizeof(float2))         // 20480
#define SMEM_TOTAL   (SMEM_W_BYTES + SMEM_X_BYTES)              // 102400

__global__ void __launch_bounds__(256, 2) k_gemm(const float* __restrict__ h_in,
                                                 const float* __restrict__ W,
                                                 float* __restrict__ out, int N) {
    extern __shared__ unsigned char smem_raw[];
    float2* s_w = (float2*)smem_raw;                               // [k*64 + p]
    float2* s_x = (float2*)(smem_raw + SMEM_W_BYTES);              // [n*K_TOT + k], {v,v}
    int tid = threadIdx.x;
    int p   = tid & 63;
    int sel = tid >> 6;

    // Load W pairs once per block: s_w[k*64+p] = {W[2p][k], W[2p+1][k]}
    for (int idx = tid; idx < K_TOT * 64; idx += 256) {
        int k = idx >> 6;
        int q = idx & 63;
        s_w[idx] = make_float2(W[(size_t)(2 * q) * K_TOT + k],
                               W[(size_t)(2 * q + 1) * K_TOT + k]);
    }

    const unsigned long long* wl = (const unsigned long long*)s_w;
    const unsigned long long* xl = (const unsigned long long*)s_x;

    int nGroups = (N + GEMM_NB - 1) / GEMM_NB;
    for (int g = blockIdx.x; g < nGroups; g += gridDim.x) {
        int base = g * GEMM_NB;
        __syncthreads();   // previous tile fully consumed (also orders W load on 1st iter)
        // stage x for 16 nodes, duplicated into both f32x2 lanes
        for (int idx = tid; idx < GEMM_NB * K_TOT; idx += 256) {
            int n = idx / K_TOT;
            int k = idx - n * K_TOT;
            int node = base + n;
            float v = 0.f;
            if (node < N)
                v = (k < IN_SIZE) ? h_in[(size_t)node * IN_SIZE + k]
                                  : g_agg[(size_t)node * E_SIZE + (k - IN_SIZE)];
            s_x[idx] = make_float2(v, v);
        }
        __syncthreads();

        const unsigned long long* x0 = xl + (size_t)(sel * 4 + 0) * K_TOT;
        const unsigned long long* x1 = xl + (size_t)(sel * 4 + 1) * K_TOT;
        const unsigned long long* x2 = xl + (size_t)(sel * 4 + 2) * K_TOT;
        const unsigned long long* x3 = xl + (size_t)(sel * 4 + 3) * K_TOT;

        unsigned long long a0 = 0ull, a1 = 0ull, a2 = 0ull, a3 = 0ull;  // {0.f,0.f}
#pragma unroll 8
        for (int k = 0; k < K_TOT; ++k) {
            unsigned long long w = wl[k * 64 + p];
            asm("fma.rn.f32x2 %0, %1, %2, %0;" : "+l"(a0) : "l"(w), "l"(x0[k]));
            asm("fma.rn.f32x2 %0, %1, %2, %0;" : "+l"(a1) : "l"(w), "l"(x1[k]));
            asm("fma.rn.f32x2 %0, %1, %2, %0;" : "+l"(a2) : "l"(w), "l"(x2[k]));
            asm("fma.rn.f32x2 %0, %1, %2, %0;" : "+l"(a3) : "l"(w), "l"(x3[k]));
        }

        union Cvt { unsigned long long u; float2 f; } cv;
        int n0 = base + sel * 4;
        if (n0 + 0 < N) { cv.u = a0; *(float2*)(out + (size_t)(n0 + 0) * H_SIZE + 2 * p) = cv.f; }
        if (n0 + 1 < N) { cv.u = a1; *(float2*)(out + (size_t)(n0 + 1) * H_SIZE + 2 * p) = cv.f; }
        if (n0 + 2 < N) { cv.u = a2; *(float2*)(out + (size_t)(n0 + 2) * H_SIZE + 2 * p) = cv.f; }
        if (n0 + 3 < N) { cv.u = a3; *(float2*)(out + (size_t)(n0 + 3) * H_SIZE + 2 * p) = cv.f; }
    }
}

// ---------------- launch ----------------
extern "C" void kernel_launch(void* const* d_in, const int* in_sizes, int n_in,
                              void* d_out, int out_size) {
    const float* h_in = (const float*)d_in[0];
    const float* ef   = (const float*)d_in[1];
    const int*   dst  = (const int*)d_in[2];
    const float* W    = (const float*)d_in[3];
    float* out = (float*)d_out;

    int N = in_sizes[0] / IN_SIZE;
    int E = in_sizes[2];
    if (N > N_MAX) N = N_MAX;
    if (E > E_MAX) E = E_MAX;

    // Idempotent, host-side (not a stream op) — legal under graph capture.
    cudaFuncSetAttribute(k_gemm, cudaFuncAttributeMaxDynamicSharedMemorySize, SMEM_TOTAL);

    k_zero<<<(N + 255) / 256, 256>>>(N);
    k_hist<<<(E + 255) / 256, 256>>>(dst, E);
    k_scan<<<1, 1024>>>(N);
    k_scatter<<<(E + 255) / 256, 256>>>(dst, E);

    int warps_per_block = 256 / 32;
    int np_blocks = (N + warps_per_block - 1) / warps_per_block;
    k_nodepass<<<np_blocks, 256>>>(ef, N);

    int nGroups = (N + GEMM_NB - 1) / GEMM_NB;
    int gemm_blocks = nGroups < 296 ? nGroups : 296;
    k_gemm<<<gemm_blocks, 256, SMEM_TOTAL>>>(h_in, W, out, N);
}

// round 3
// speedup vs baseline: 1.1612x; 1.1612x over previous
#include <cuda_runtime.h>
#include <cstdint>

#define IN_SIZE   128
#define E_SIZE    32
#define H_SIZE    128
#define K_TOT     160
#define THRESH    0.5f

#define N_MAX     50000
#define E_MAX     1600000

typedef unsigned long long u64;

// ---------------- device scratch ----------------
__device__ int   g_cnt[N_MAX];
__device__ int   g_offs[N_MAX + 1];
__device__ int   g_cur[N_MAX];
__device__ int   g_eidx[E_MAX];
__device__ float g_agg[(size_t)N_MAX * E_SIZE];
__device__ int   g_bsum[256];   // block partial sums for scan (<=196 used)

// ---------------- K0: zero histogram ----------------
__global__ void k_zero(int N) {
    int i = blockIdx.x * blockDim.x + threadIdx.x;
    if (i < N) g_cnt[i] = 0;
}

// ---------------- K1: degree histogram ----------------
__global__ void k_hist(const int* __restrict__ dst, int E) {
    int i = blockIdx.x * blockDim.x + threadIdx.x;
    if (i < E) atomicAdd(&g_cnt[dst[i]], 1);
}

// ---------------- scan stage 1: per-block (256-elem) sums ----------------
__global__ void k_s1(int N) {
    __shared__ int red[256];
    int t = threadIdx.x;
    int i = blockIdx.x * 256 + t;
    red[t] = (i < N) ? g_cnt[i] : 0;
    __syncthreads();
#pragma unroll
    for (int s = 128; s > 0; s >>= 1) {
        if (t < s) red[t] += red[t + s];
        __syncthreads();
    }
    if (t == 0) g_bsum[blockIdx.x] = red[0];
}

// ---------------- scan stage 2: single-block scan of block sums ----------------
__global__ void k_s2(int NB, int N) {
    __shared__ int s[256];
    int t = threadIdx.x;
    int v = (t < NB) ? g_bsum[t] : 0;
    s[t] = v;
    __syncthreads();
#pragma unroll
    for (int d = 1; d < 256; d <<= 1) {
        int x = (t >= d) ? s[t - d] : 0;
        __syncthreads();
        if (t >= d) s[t] += x;
        __syncthreads();
    }
    if (t < NB) g_bsum[t] = s[t] - v;       // exclusive base per block
    if (t == 255) g_offs[N] = s[255];       // total == E
}

// ---------------- scan stage 3: per-block exclusive scan + base ----------------
__global__ void k_s3(int N) {
    __shared__ int s[256];
    int t = threadIdx.x;
    int i = blockIdx.x * 256 + t;
    int v = (i < N) ? g_cnt[i] : 0;
    s[t] = v;
    __syncthreads();
#pragma unroll
    for (int d = 1; d < 256; d <<= 1) {
        int x = (t >= d) ? s[t - d] : 0;
        __syncthreads();
        if (t >= d) s[t] += x;
        __syncthreads();
    }
    if (i < N) {
        int off = g_bsum[blockIdx.x] + s[t] - v;
        g_offs[i] = off;
        g_cur[i]  = off;
    }
}

// ---------------- K3: scatter edge indices into CSR ----------------
__global__ void k_scatter(const int* __restrict__ dst, int E) {
    int i = blockIdx.x * blockDim.x + threadIdx.x;
    if (i < E) {
        int d = dst[i];
        int p = atomicAdd(&g_cur[d], 1);
        g_eidx[p] = i;
    }
}

// ---------------- K4: per-node gather pass (warp per node) ----------------
__global__ void k_nodepass(const float* __restrict__ ef, int N) {
    int warp = (blockIdx.x * blockDim.x + threadIdx.x) >> 5;
    if (warp >= N) return;
    int lane = threadIdx.x & 31;

    int start = __ldg(&g_offs[warp]);
    int end   = __ldg(&g_offs[warp + 1]);
    int deg   = end - start;

    float esum = 0.f;
#pragma unroll 4
    for (int i = start; i < end; ++i) {
        int e = __ldg(&g_eidx[i]);
        esum += __ldg(&ef[(size_t)e * E_SIZE + lane]);
    }
    float hk = (deg > 0) ? (esum / (float)deg) : 0.f;

    float nh = hk * hk;
#pragma unroll
    for (int o = 16; o; o >>= 1) nh += __shfl_xor_sync(0xffffffffu, nh, o);

    float ssum = 0.f, scnt = 0.f;
    int i = start;
    for (; i + 1 < end; i += 2) {
        int e0 = __ldg(&g_eidx[i]);
        int e1 = __ldg(&g_eidx[i + 1]);
        float v0 = __ldg(&ef[(size_t)e0 * E_SIZE + lane]);
        float v1 = __ldg(&ef[(size_t)e1 * E_SIZE + lane]);
        float d0 = hk * v0, q0 = v0 * v0;
        float d1 = hk * v1, q1 = v1 * v1;
#pragma unroll
        for (int o = 16; o; o >>= 1) {
            d0 += __shfl_xor_sync(0xffffffffu, d0, o);
            q0 += __shfl_xor_sync(0xffffffffu, q0, o);
            d1 += __shfl_xor_sync(0xffffffffu, d1, o);
            q1 += __shfl_xor_sync(0xffffffffu, q1, o);
        }
        float c0 = d0 / sqrtf(nh * q0);   // NaN (den==0) -> excluded, matches ref
        float c1 = d1 / sqrtf(nh * q1);
        if (c0 < THRESH) { ssum += v0; scnt += 1.f; }
        if (c1 < THRESH) { ssum += v1; scnt += 1.f; }
    }
    if (i < end) {
        int e0 = __ldg(&g_eidx[i]);
        float v0 = __ldg(&ef[(size_t)e0 * E_SIZE + lane]);
        float d0 = hk * v0, q0 = v0 * v0;
#pragma unroll
        for (int o = 16; o; o >>= 1) {
            d0 += __shfl_xor_sync(0xffffffffu, d0, o);
            q0 += __shfl_xor_sync(0xffffffffu, q0, o);
        }
        float c0 = d0 / sqrtf(nh * q0);
        if (c0 < THRESH) { ssum += v0; scnt += 1.f; }
    }

    float agg = (scnt > 0.f) ? (ssum / scnt) : hk;
    g_agg[(size_t)warp * E_SIZE + lane] = agg;
}

// ---------------- K5: GEMM out[n][h] = sum_k x[n][k] * W[h][k] ----------------
// Persistent blocks. Register tile: 8 nodes x 4 h (2 f32x2 h-pairs) per thread.
// smem: s_w[k][h] floats, row stride 130 (pad -> 2-way max on STS, broadcast LDS);
//       s_x[k][n] as duplicated {v,v} u64, row stride 65 u64.
// Thread map (256 thr): tn = tid&7 -> nodes {tn+8i}, th = tid>>3 -> h in [th*4, th*4+4).
#define TILE_N   64
#define SW_STRIDE 130                    // floats per k-row of s_w
#define SX_STRIDE 65                     // u64 per k-row of s_x
#define SMEM_W_BYTES (K_TOT * SW_STRIDE * 4)   // 83200
#define SMEM_X_BYTES (K_TOT * SX_STRIDE * 8)   // 83200
#define SMEM_TOTAL   (SMEM_W_BYTES + SMEM_X_BYTES)

__global__ void __launch_bounds__(256, 1) k_gemm(const float* __restrict__ h_in,
                                                 const float* __restrict__ W,
                                                 float* __restrict__ out, int N) {
    extern __shared__ unsigned char smem_raw[];
    float* s_w = (float*)smem_raw;
    u64*   s_x = (u64*)(smem_raw + SMEM_W_BYTES);
    int tid = threadIdx.x;
    int tn  = tid & 7;
    int th  = tid >> 3;

    // ---- load W once per block: s_w[k*SW_STRIDE + h] = W[h*K_TOT + k] ----
    // gmem reads coalesced (consecutive tid -> consecutive k of same h row).
    for (int idx = tid; idx < H_SIZE * K_TOT; idx += 256) {
        int h = idx / K_TOT;
        int k = idx - h * K_TOT;
        s_w[k * SW_STRIDE + h] = W[idx];
    }

    int nTiles = (N + TILE_N - 1) / TILE_N;
    for (int g = blockIdx.x; g < nTiles; g += gridDim.x) {
        int base = g * TILE_N;
        __syncthreads();   // s_x free (prev tile consumed); also orders W on 1st iter
        // ---- stage x tile, duplicated into both f32x2 lanes ----
        for (int idx = tid; idx < TILE_N * K_TOT; idx += 256) {
            int n = idx / K_TOT;
            int k = idx - n * K_TOT;
            int node = base + n;
            float v = 0.f;
            if (node < N)
                v = (k < IN_SIZE) ? h_in[(size_t)node * IN_SIZE + k]
                                  : g_agg[(size_t)node * E_SIZE + (k - IN_SIZE)];
            *(float2*)&s_x[k * SX_STRIDE + n] = make_float2(v, v);
        }
        __syncthreads();

        u64 acc[8][2];
#pragma unroll
        for (int i = 0; i < 8; ++i) { acc[i][0] = 0ull; acc[i][1] = 0ull; }

        const float* wp = s_w + th * 4;
        const u64*   xp = s_x + tn;
#pragma unroll 4
        for (int k = 0; k < K_TOT; ++k) {
            u64 w0 = *(const u64*)(wp + (size_t)k * SW_STRIDE);       // {W[h0],W[h1]}
            u64 w1 = *(const u64*)(wp + (size_t)k * SW_STRIDE + 2);   // {W[h2],W[h3]}
            const u64* xr = xp + (size_t)k * SX_STRIDE;
#pragma unroll
            for (int i = 0; i < 8; ++i) {
                u64 xv = xr[i * 8];                                    // {v,v} node tn+8i
                asm("fma.rn.f32x2 %0, %1, %2, %0;" : "+l"(acc[i][0]) : "l"(w0), "l"(xv));
                asm("fma.rn.f32x2 %0, %1, %2, %0;" : "+l"(acc[i][1]) : "l"(w1), "l"(xv));
            }
        }

        union Cvt { u64 u; float2 f; } cv;
#pragma unroll
        for (int i = 0; i < 8; ++i) {
            int node = base + tn + 8 * i;
            if (node < N) {
                float* o = out + (size_t)node * H_SIZE + th * 4;
                cv.u = acc[i][0]; *(float2*)(o)     = cv.f;
                cv.u = acc[i][1]; *(float2*)(o + 2) = cv.f;
            }
        }
    }
}

// ---------------- launch ----------------
extern "C" void kernel_launch(void* const* d_in, const int* in_sizes, int n_in,
                              void* d_out, int out_size) {
    const float* h_in = (const float*)d_in[0];
    const float* ef   = (const float*)d_in[1];
    const int*   dst  = (const int*)d_in[2];
    const float* W    = (const float*)d_in[3];
    float* out = (float*)d_out;

    int N = in_sizes[0] / IN_SIZE;
    int E = in_sizes[2];
    if (N > N_MAX) N = N_MAX;
    if (E > E_MAX) E = E_MAX;

    cudaFuncSetAttribute(k_gemm, cudaFuncAttributeMaxDynamicSharedMemorySize, SMEM_TOTAL);

    int NB = (N + 255) / 256;   // <= 196

    k_zero<<<(N + 255) / 256, 256>>>(N);
    k_hist<<<(E + 255) / 256, 256>>>(dst, E);
    k_s1<<<NB, 256>>>(N);
    k_s2<<<1, 256>>>(NB, N);
    k_s3<<<NB, 256>>>(N);
    k_scatter<<<(E + 255) / 256, 256>>>(dst, E);

    int np_blocks = (N + 7) / 8;              // 8 warps (nodes) per 256-thr block
    k_nodepass<<<np_blocks, 256>>>(ef, N);

    int nTiles = (N + TILE_N - 1) / TILE_N;
    int gemm_blocks = nTiles < 148 ? nTiles : 148;
    k_gemm<<<gemm_blocks, 256, SMEM_TOTAL>>>(h_in, W, out, N);
}

// round 7
// speedup vs baseline: 1.3754x; 1.1844x over previous
#include <cuda_runtime.h>
#include <cstdint>

#define IN_SIZE   128
#define E_SIZE    32
#define H_SIZE    128
#define K_TOT     160
#define THRESH    0.5f

#define N_MAX     50000
#define E_MAX     1600000

typedef unsigned long long u64;

// ---------------- device scratch ----------------
__device__ int   g_cnt[N_MAX];
__device__ int   g_offs[N_MAX + 1];
__device__ int   g_cur[N_MAX];
__device__ int   g_eidx[E_MAX];
__device__ float g_agg[(size_t)N_MAX * E_SIZE];
__device__ int   g_bsum[256];

// ---------------- K0: zero histogram ----------------
__global__ void k_zero(int N) {
    int i = blockIdx.x * blockDim.x + threadIdx.x;
    if (i < N) g_cnt[i] = 0;
}

// ---------------- K1: degree histogram ----------------
__global__ void k_hist(const int* __restrict__ dst, int E) {
    int i = blockIdx.x * blockDim.x + threadIdx.x;
    if (i < E) atomicAdd(&g_cnt[dst[i]], 1);
}

// ---------------- scan stage 1: per-block (256-elem) sums ----------------
__global__ void k_s1(int N) {
    __shared__ int red[256];
    int t = threadIdx.x;
    int i = blockIdx.x * 256 + t;
    red[t] = (i < N) ? g_cnt[i] : 0;
    __syncthreads();
#pragma unroll
    for (int s = 128; s > 0; s >>= 1) {
        if (t < s) red[t] += red[t + s];
        __syncthreads();
    }
    if (t == 0) g_bsum[blockIdx.x] = red[0];
}

// ---------------- scan stage 2: single-block scan of block sums ----------------
__global__ void k_s2(int NB, int N) {
    __shared__ int s[256];
    int t = threadIdx.x;
    int v = (t < NB) ? g_bsum[t] : 0;
    s[t] = v;
    __syncthreads();
#pragma unroll
    for (int d = 1; d < 256; d <<= 1) {
        int x = (t >= d) ? s[t - d] : 0;
        __syncthreads();
        if (t >= d) s[t] += x;
        __syncthreads();
    }
    if (t < NB) g_bsum[t] = s[t] - v;
    if (t == 255) g_offs[N] = s[255];
}

// ---------------- scan stage 3: per-block exclusive scan + base ----------------
__global__ void k_s3(int N) {
    __shared__ int s[256];
    int t = threadIdx.x;
    int i = blockIdx.x * 256 + t;
    int v = (i < N) ? g_cnt[i] : 0;
    s[t] = v;
    __syncthreads();
#pragma unroll
    for (int d = 1; d < 256; d <<= 1) {
        int x = (t >= d) ? s[t - d] : 0;
        __syncthreads();
        if (t >= d) s[t] += x;
        __syncthreads();
    }
    if (i < N) {
        int off = g_bsum[blockIdx.x] + s[t] - v;
        g_offs[i] = off;
        g_cur[i]  = off;
    }
}

// ---------------- K3: scatter edge indices into CSR ----------------
__global__ void k_scatter(const int* __restrict__ dst, int E) {
    int i = blockIdx.x * blockDim.x + threadIdx.x;
    if (i < E) {
        int d = dst[i];
        int p = atomicAdd(&g_cur[d], 1);
        g_eidx[p] = i;
    }
}

// ---------------- K4: per-node gather (warp per node, 4 lanes per edge) ----------------
// slot = lane&3 owns features [8*slot, 8*slot+8); egrp = lane>>2 -> edge within batch of 8.
// All loops have warp-uniform trip counts so full-mask shuffles are always converged.
__global__ void __launch_bounds__(256) k_nodepass(const float* __restrict__ ef, int N) {
    int warp = (blockIdx.x * blockDim.x + threadIdx.x) >> 5;
    if (warp >= N) return;
    int lane = threadIdx.x & 31;
    int slot = lane & 3;
    int egrp = lane >> 2;

    int start = __ldg(&g_offs[warp]);
    int end   = __ldg(&g_offs[warp + 1]);
    int deg   = end - start;
    int nb    = (deg + 7) >> 3;          // warp-uniform batch count

    const float* efs = ef + slot * 8;

    // ---- pass A: per-slot partial sums ----
    float es[8];
#pragma unroll
    for (int j = 0; j < 8; ++j) es[j] = 0.f;

    for (int it = 0; it < nb; ++it) {
        int b = start + it * 8 + egrp;
        if (b < end) {
            int e = __ldg(&g_eidx[b]);
            const float4* p = (const float4*)(efs + (size_t)e * E_SIZE);
            float4 a = __ldg(p), c = __ldg(p + 1);
            es[0] += a.x; es[1] += a.y; es[2] += a.z; es[3] += a.w;
            es[4] += c.x; es[5] += c.y; es[6] += c.z; es[7] += c.w;
        }
    }
    // reduce over egrp lanes (xor 4,8,16) — post-loop, warp converged
#pragma unroll
    for (int o = 4; o <= 16; o <<= 1)
#pragma unroll
        for (int j = 0; j < 8; ++j) es[j] += __shfl_xor_sync(0xffffffffu, es[j], o);

    float hk[8];
    float fdeg = (float)deg;
#pragma unroll
    for (int j = 0; j < 8; ++j) hk[j] = (deg > 0) ? (es[j] / fdeg) : 0.f;

    float nh = 0.f;
#pragma unroll
    for (int j = 0; j < 8; ++j) nh += hk[j] * hk[j];
    nh += __shfl_xor_sync(0xffffffffu, nh, 1);
    nh += __shfl_xor_sync(0xffffffffu, nh, 2);

    // ---- pass B: cosine filter + masked accumulation (uniform trip count) ----
    float ss[8];
    float scnt = 0.f;
#pragma unroll
    for (int j = 0; j < 8; ++j) ss[j] = 0.f;

    for (int it = 0; it < nb; ++it) {
        int b = start + it * 8 + egrp;
        bool valid = (b < end);
        float v0 = 0.f, v1 = 0.f, v2 = 0.f, v3 = 0.f;
        float v4 = 0.f, v5 = 0.f, v6 = 0.f, v7 = 0.f;
        if (valid) {
            int e = __ldg(&g_eidx[b]);
            const float4* p = (const float4*)(efs + (size_t)e * E_SIZE);
            float4 a = __ldg(p), c = __ldg(p + 1);
            v0 = a.x; v1 = a.y; v2 = a.z; v3 = a.w;
            v4 = c.x; v5 = c.y; v6 = c.z; v7 = c.w;
        }
        float d = hk[0]*v0 + hk[1]*v1 + hk[2]*v2 + hk[3]*v3
                + hk[4]*v4 + hk[5]*v5 + hk[6]*v6 + hk[7]*v7;
        float q = v0*v0 + v1*v1 + v2*v2 + v3*v3
                + v4*v4 + v5*v5 + v6*v6 + v7*v7;
        // reduce d,q across the 4 slot lanes — whole warp executes these
        d += __shfl_xor_sync(0xffffffffu, d, 1);
        q += __shfl_xor_sync(0xffffffffu, q, 1);
        d += __shfl_xor_sync(0xffffffffu, d, 2);
        q += __shfl_xor_sync(0xffffffffu, q, 2);
        float cc = d / sqrtf(nh * q);   // invalid/zero rows: 0/0 -> NaN -> excluded (matches ref)
        if (cc < THRESH) {
            ss[0] += v0; ss[1] += v1; ss[2] += v2; ss[3] += v3;
            ss[4] += v4; ss[5] += v5; ss[6] += v6; ss[7] += v7;
            scnt += valid ? 1.f : 0.f;
        }
    }
    // reduce ssum/scnt over egrp lanes
#pragma unroll
    for (int o = 4; o <= 16; o <<= 1) {
        scnt += __shfl_xor_sync(0xffffffffu, scnt, o);
#pragma unroll
        for (int j = 0; j < 8; ++j) ss[j] += __shfl_xor_sync(0xffffffffu, ss[j], o);
    }

    if (egrp == 0) {
        float outv[8];
#pragma unroll
        for (int j = 0; j < 8; ++j)
            outv[j] = (scnt > 0.f) ? (ss[j] / scnt) : hk[j];
        float4* dsta = (float4*)(g_agg + (size_t)warp * E_SIZE + slot * 8);
        dsta[0] = make_float4(outv[0], outv[1], outv[2], outv[3]);
        dsta[1] = make_float4(outv[4], outv[5], outv[6], outv[7]);
    }
}

// ---------------- K5: GEMM out[n][h] = sum_k x[n][k] * W[h][k] ----------------
#define TILE_N   64
#define SW_STRIDE 130
#define SX_STRIDE 65
#define SMEM_W_BYTES (K_TOT * SW_STRIDE * 4)
#define SMEM_X_BYTES (K_TOT * SX_STRIDE * 8)
#define SMEM_TOTAL   (SMEM_W_BYTES + SMEM_X_BYTES)

__global__ void __launch_bounds__(256, 1) k_gemm(const float* __restrict__ h_in,
                                                 const float* __restrict__ W,
                                                 float* __restrict__ out, int N) {
    extern __shared__ unsigned char smem_raw[];
    float* s_w = (float*)smem_raw;
    u64*   s_x = (u64*)(smem_raw + SMEM_W_BYTES);
    int tid = threadIdx.x;
    int tn  = tid & 7;
    int th  = tid >> 3;

    for (int idx = tid; idx < H_SIZE * K_TOT; idx += 256) {
        int h = idx / K_TOT;
        int k = idx - h * K_TOT;
        s_w[k * SW_STRIDE + h] = W[idx];
    }

    int nTiles = (N + TILE_N - 1) / TILE_N;
    for (int g = blockIdx.x; g < nTiles; g += gridDim.x) {
        int base = g * TILE_N;
        __syncthreads();
        for (int idx = tid; idx < TILE_N * K_TOT; idx += 256) {
            int n = idx / K_TOT;
            int k = idx - n * K_TOT;
            int node = base + n;
            float v = 0.f;
            if (node < N)
                v = (k < IN_SIZE) ? h_in[(size_t)node * IN_SIZE + k]
                                  : g_agg[(size_t)node * E_SIZE + (k - IN_SIZE)];
            *(float2*)&s_x[k * SX_STRIDE + n] = make_float2(v, v);
        }
        __syncthreads();

        u64 acc[8][2];
#pragma unroll
        for (int i = 0; i < 8; ++i) { acc[i][0] = 0ull; acc[i][1] = 0ull; }

        const float* wp = s_w + th * 4;
        const u64*   xp = s_x + tn;
#pragma unroll 4
        for (int k = 0; k < K_TOT; ++k) {
            u64 w0 = *(const u64*)(wp + (size_t)k * SW_STRIDE);
            u64 w1 = *(const u64*)(wp + (size_t)k * SW_STRIDE + 2);
            const u64* xr = xp + (size_t)k * SX_STRIDE;
#pragma unroll
            for (int i = 0; i < 8; ++i) {
                u64 xv = xr[i * 8];
                asm("fma.rn.f32x2 %0, %1, %2, %0;" : "+l"(acc[i][0]) : "l"(w0), "l"(xv));
                asm("fma.rn.f32x2 %0, %1, %2, %0;" : "+l"(acc[i][1]) : "l"(w1), "l"(xv));
            }
        }

        union Cvt { u64 u; float2 f; } cv;
#pragma unroll
        for (int i = 0; i < 8; ++i) {
            int node = base + tn + 8 * i;
            if (node < N) {
                float* o = out + (size_t)node * H_SIZE + th * 4;
                cv.u = acc[i][0]; *(float2*)(o)     = cv.f;
                cv.u = acc[i][1]; *(float2*)(o + 2) = cv.f;
            }
        }
    }
}

// ---------------- launch ----------------
extern "C" void kernel_launch(void* const* d_in, const int* in_sizes, int n_in,
                              void* d_out, int out_size) {
    const float* h_in = (const float*)d_in[0];
    const float* ef   = (const float*)d_in[1];
    const int*   dst  = (const int*)d_in[2];
    const float* W    = (const float*)d_in[3];
    float* out = (float*)d_out;

    int N = in_sizes[0] / IN_SIZE;
    int E = in_sizes[2];
    if (N > N_MAX) N = N_MAX;
    if (E > E_MAX) E = E_MAX;

    cudaFuncSetAttribute(k_gemm, cudaFuncAttributeMaxDynamicSharedMemorySize, SMEM_TOTAL);

    int NB = (N + 255) / 256;

    k_zero<<<(N + 255) / 256, 256>>>(N);
    k_hist<<<(E + 255) / 256, 256>>>(dst, E);
    k_s1<<<NB, 256>>>(N);
    k_s2<<<1, 256>>>(NB, N);
    k_s3<<<NB, 256>>>(N);
    k_scatter<<<(E + 255) / 256, 256>>>(dst, E);

    int np_blocks = (N + 7) / 8;
    k_nodepass<<<np_blocks, 256>>>(ef, N);

    int nTiles = (N + TILE_N - 1) / TILE_N;
    int gemm_blocks = nTiles < 148 ? nTiles : 148;
    k_gemm<<<gemm_blocks, 256, SMEM_TOTAL>>>(h_in, W, out, N);
}

// round 8
// speedup vs baseline: 1.3760x; 1.0004x over previous
#include <cuda_runtime.h>
#include <cstdint>

#define IN_SIZE   128
#define E_SIZE    32
#define H_SIZE    128
#define K_TOT     160
#define THRESH    0.5f

#define N_MAX     50000
#define E_MAX     1600000

typedef unsigned long long u64;

// ---------------- device scratch ----------------
__device__ int   g_cnt[N_MAX];
__device__ int   g_offs[N_MAX + 1];
__device__ int   g_cur[N_MAX];
__device__ int   g_eidx[E_MAX];
__device__ float g_agg[(size_t)N_MAX * E_SIZE];
__device__ int   g_bsum[256];

// ---------------- K0: zero histogram ----------------
__global__ void k_zero(int N) {
    int i = blockIdx.x * blockDim.x + threadIdx.x;
    if (i < N) g_cnt[i] = 0;
}

// ---------------- K1: degree histogram ----------------
__global__ void k_hist(const int* __restrict__ dst, int E) {
    int i = blockIdx.x * blockDim.x + threadIdx.x;
    if (i < E) atomicAdd(&g_cnt[dst[i]], 1);
}

// ---------------- scan stage 1: per-block (256-elem) sums ----------------
__global__ void k_s1(int N) {
    __shared__ int red[256];
    int t = threadIdx.x;
    int i = blockIdx.x * 256 + t;
    red[t] = (i < N) ? g_cnt[i] : 0;
    __syncthreads();
#pragma unroll
    for (int s = 128; s > 0; s >>= 1) {
        if (t < s) red[t] += red[t + s];
        __syncthreads();
    }
    if (t == 0) g_bsum[blockIdx.x] = red[0];
}

// ---------------- scan stage 2: single-block scan of block sums ----------------
__global__ void k_s2(int NB, int N) {
    __shared__ int s[256];
    int t = threadIdx.x;
    int v = (t < NB) ? g_bsum[t] : 0;
    s[t] = v;
    __syncthreads();
#pragma unroll
    for (int d = 1; d < 256; d <<= 1) {
        int x = (t >= d) ? s[t - d] : 0;
        __syncthreads();
        if (t >= d) s[t] += x;
        __syncthreads();
    }
    if (t < NB) g_bsum[t] = s[t] - v;
    if (t == 255) g_offs[N] = s[255];
}

// ---------------- scan stage 3: per-block exclusive scan + base ----------------
__global__ void k_s3(int N) {
    __shared__ int s[256];
    int t = threadIdx.x;
    int i = blockIdx.x * 256 + t;
    int v = (i < N) ? g_cnt[i] : 0;
    s[t] = v;
    __syncthreads();
#pragma unroll
    for (int d = 1; d < 256; d <<= 1) {
        int x = (t >= d) ? s[t - d] : 0;
        __syncthreads();
        if (t >= d) s[t] += x;
        __syncthreads();
    }
    if (i < N) {
        int off = g_bsum[blockIdx.x] + s[t] - v;
        g_offs[i] = off;
        g_cur[i]  = off;
    }
}

// ---------------- K3: scatter edge indices into CSR ----------------
__global__ void k_scatter(const int* __restrict__ dst, int E) {
    int i = blockIdx.x * blockDim.x + threadIdx.x;
    if (i < E) {
        int d = dst[i];
        int p = atomicAdd(&g_cur[d], 1);
        g_eidx[p] = i;
    }
}

// ---------------- K4: per-node gather, warp per node, 4 lanes per edge,
// warp-private smem row cache so each edge row is fetched from DRAM exactly once.
// slot = lane&3 owns features [8*slot,8*slot+8); egrp = lane>>2 -> edge in batch of 8.
// Cache layout [warp][it][j][lane] (float4): every LDS/STS.128 is lane-stride-16B
// -> each 8-lane phase covers 128B contiguous -> conflict-free. Per-lane self-read
// only, so no __syncwarp needed. All loop trip counts are warp-uniform.
#define CAPIT 6                 // cached batches: 48 edges per warp (6KB)
__global__ void __launch_bounds__(256) k_nodepass(const float* __restrict__ ef, int N) {
    __shared__ float4 sc[8 * CAPIT * 2 * 32];   // 49152 bytes
    int warp = (blockIdx.x * blockDim.x + threadIdx.x) >> 5;
    if (warp >= N) return;
    int lane = threadIdx.x & 31;
    int slot = lane & 3;
    int egrp = lane >> 2;
    int w    = (threadIdx.x >> 5);
    int cbase = w * CAPIT * 64 + lane;          // float4 index; +it*64, +32 for j=1

    int start = __ldg(&g_offs[warp]);
    int end   = __ldg(&g_offs[warp + 1]);
    int deg   = end - start;
    int nb    = (deg + 7) >> 3;                 // warp-uniform batch count

    // ---- pass A: gather + accumulate + cache ----
    float es[8];
#pragma unroll
    for (int j = 0; j < 8; ++j) es[j] = 0.f;

#define BODYA(IT)  {                                                          \
        int b = start + (IT) * 8 + egrp;                                      \
        float4 a = make_float4(0.f, 0.f, 0.f, 0.f), c = a;                    \
        if (b < end) {                                                        \
            int e = __ldg(&g_eidx[b]);                                        \
            const float4* p = (const float4*)(ef + (size_t)e * E_SIZE) + slot * 2; \
            a = __ldg(p); c = __ldg(p + 1);                                   \
        }                                                                     \
        es[0] += a.x; es[1] += a.y; es[2] += a.z; es[3] += a.w;               \
        es[4] += c.x; es[5] += c.y; es[6] += c.z; es[7] += c.w;               \
        if ((IT) < CAPIT) {                                                   \
            sc[cbase + (IT) * 64]      = a;                                   \
            sc[cbase + (IT) * 64 + 32] = c;                                   \
        }                                                                     \
    }

    int it = 0;
    for (; it + 2 <= nb; it += 2) { BODYA(it) BODYA(it + 1) }
    if (it < nb) { BODYA(it) }
#undef BODYA

    // reduce over egrp lanes (xor 4,8,16) — warp converged here
#pragma unroll
    for (int o = 4; o <= 16; o <<= 1)
#pragma unroll
        for (int j = 0; j < 8; ++j) es[j] += __shfl_xor_sync(0xffffffffu, es[j], o);

    float hk[8];
    float fdeg = (float)deg;
#pragma unroll
    for (int j = 0; j < 8; ++j) hk[j] = (deg > 0) ? (es[j] / fdeg) : 0.f;

    float nh = 0.f;
#pragma unroll
    for (int j = 0; j < 8; ++j) nh += hk[j] * hk[j];
    nh += __shfl_xor_sync(0xffffffffu, nh, 1);
    nh += __shfl_xor_sync(0xffffffffu, nh, 2);

    // ---- pass B: cosine filter + masked accumulation ----
    float ss[8];
    float scnt = 0.f;
#pragma unroll
    for (int j = 0; j < 8; ++j) ss[j] = 0.f;

#define BODYB(AX, CX)  {                                                      \
        float v0 = (AX).x, v1 = (AX).y, v2 = (AX).z, v3 = (AX).w;             \
        float v4 = (CX).x, v5 = (CX).y, v6 = (CX).z, v7 = (CX).w;             \
        float d = hk[0]*v0 + hk[1]*v1 + hk[2]*v2 + hk[3]*v3                   \
                + hk[4]*v4 + hk[5]*v5 + hk[6]*v6 + hk[7]*v7;                  \
        float q = v0*v0 + v1*v1 + v2*v2 + v3*v3                               \
                + v4*v4 + v5*v5 + v6*v6 + v7*v7;                              \
        d += __shfl_xor_sync(0xffffffffu, d, 1);                              \
        q += __shfl_xor_sync(0xffffffffu, q, 1);                              \
        d += __shfl_xor_sync(0xffffffffu, d, 2);                              \
        q += __shfl_xor_sync(0xffffffffu, q, 2);                              \
        float cc = d / sqrtf(nh * q);  /* zero/pad rows: 0/0 -> NaN -> excluded */ \
        if (cc < THRESH) {                                                    \
            ss[0] += v0; ss[1] += v1; ss[2] += v2; ss[3] += v3;               \
            ss[4] += v4; ss[5] += v5; ss[6] += v6; ss[7] += v7;               \
            scnt += 1.f;                                                      \
        }                                                                     \
    }

    int nc = nb < CAPIT ? nb : CAPIT;           // warp-uniform
    for (it = 0; it < nc; ++it) {
        float4 a = sc[cbase + it * 64];
        float4 c = sc[cbase + it * 64 + 32];
        BODYB(a, c)
    }
    for (it = CAPIT; it < nb; ++it) {           // rare overflow: reread (L2-hot)
        int b = start + it * 8 + egrp;
        float4 a = make_float4(0.f, 0.f, 0.f, 0.f), c = a;
        if (b < end) {
            int e = __ldg(&g_eidx[b]);
            const float4* p = (const float4*)(ef + (size_t)e * E_SIZE) + slot * 2;
            a = __ldg(p); c = __ldg(p + 1);
        }
        BODYB(a, c)
    }
#undef BODYB

    // reduce ssum/scnt over egrp lanes
#pragma unroll
    for (int o = 4; o <= 16; o <<= 1) {
        scnt += __shfl_xor_sync(0xffffffffu, scnt, o);
#pragma unroll
        for (int j = 0; j < 8; ++j) ss[j] += __shfl_xor_sync(0xffffffffu, ss[j], o);
    }

    if (egrp == 0) {
        float outv[8];
#pragma unroll
        for (int j = 0; j < 8; ++j)
            outv[j] = (scnt > 0.f) ? (ss[j] / scnt) : hk[j];
        float4* dsta = (float4*)(g_agg + (size_t)warp * E_SIZE + slot * 8);
        dsta[0] = make_float4(outv[0], outv[1], outv[2], outv[3]);
        dsta[1] = make_float4(outv[4], outv[5], outv[6], outv[7]);
    }
}

// ---------------- K5: GEMM out[n][h] = sum_k x[n][k] * W[h][k] ----------------
#define TILE_N   64
#define SW_STRIDE 130
#define SX_STRIDE 65
#define SMEM_W_BYTES (K_TOT * SW_STRIDE * 4)
#define SMEM_X_BYTES (K_TOT * SX_STRIDE * 8)
#define SMEM_TOTAL   (SMEM_W_BYTES + SMEM_X_BYTES)

__global__ void __launch_bounds__(256, 1) k_gemm(const float* __restrict__ h_in,
                                                 const float* __restrict__ W,
                                                 float* __restrict__ out, int N) {
    extern __shared__ unsigned char smem_raw[];
    float* s_w = (float*)smem_raw;
    u64*   s_x = (u64*)(smem_raw + SMEM_W_BYTES);
    int tid = threadIdx.x;
    int tn  = tid & 7;
    int th  = tid >> 3;

    for (int idx = tid; idx < H_SIZE * K_TOT; idx += 256) {
        int h = idx / K_TOT;
        int k = idx - h * K_TOT;
        s_w[k * SW_STRIDE + h] = W[idx];
    }

    int nTiles = (N + TILE_N - 1) / TILE_N;
    for (int g = blockIdx.x; g < nTiles; g += gridDim.x) {
        int base = g * TILE_N;
        __syncthreads();
        for (int idx = tid; idx < TILE_N * K_TOT; idx += 256) {
            int n = idx / K_TOT;
            int k = idx - n * K_TOT;
            int node = base + n;
            float v = 0.f;
            if (node < N)
                v = (k < IN_SIZE) ? h_in[(size_t)node * IN_SIZE + k]
                                  : g_agg[(size_t)node * E_SIZE + (k - IN_SIZE)];
            *(float2*)&s_x[k * SX_STRIDE + n] = make_float2(v, v);
        }
        __syncthreads();

        u64 acc[8][2];
#pragma unroll
        for (int i = 0; i < 8; ++i) { acc[i][0] = 0ull; acc[i][1] = 0ull; }

        const float* wp = s_w + th * 4;
        const u64*   xp = s_x + tn;
#pragma unroll 4
        for (int k = 0; k < K_TOT; ++k) {
            u64 w0 = *(const u64*)(wp + (size_t)k * SW_STRIDE);
            u64 w1 = *(const u64*)(wp + (size_t)k * SW_STRIDE + 2);
            const u64* xr = xp + (size_t)k * SX_STRIDE;
#pragma unroll
            for (int i = 0; i < 8; ++i) {
                u64 xv = xr[i * 8];
                asm("fma.rn.f32x2 %0, %1, %2, %0;" : "+l"(acc[i][0]) : "l"(w0), "l"(xv));
                asm("fma.rn.f32x2 %0, %1, %2, %0;" : "+l"(acc[i][1]) : "l"(w1), "l"(xv));
            }
        }

        union Cvt { u64 u; float2 f; } cv;
#pragma unroll
        for (int i = 0; i < 8; ++i) {
            int node = base + tn + 8 * i;
            if (node < N) {
                float* o = out + (size_t)node * H_SIZE + th * 4;
                cv.u = acc[i][0]; *(float2*)(o)     = cv.f;
                cv.u = acc[i][1]; *(float2*)(o + 2) = cv.f;
            }
        }
    }
}

// ---------------- launch ----------------
extern "C" void kernel_launch(void* const* d_in, const int* in_sizes, int n_in,
                              void* d_out, int out_size) {
    const float* h_in = (const float*)d_in[0];
    const float* ef   = (const float*)d_in[1];
    const int*   dst  = (const int*)d_in[2];
    const float* W    = (const float*)d_in[3];
    float* out = (float*)d_out;

    int N = in_sizes[0] / IN_SIZE;
    int E = in_sizes[2];
    if (N > N_MAX) N = N_MAX;
    if (E > E_MAX) E = E_MAX;

    cudaFuncSetAttribute(k_gemm, cudaFuncAttributeMaxDynamicSharedMemorySize, SMEM_TOTAL);

    int NB = (N + 255) / 256;

    k_zero<<<(N + 255) / 256, 256>>>(N);
    k_hist<<<(E + 255) / 256, 256>>>(dst, E);
    k_s1<<<NB, 256>>>(N);
    k_s2<<<1, 256>>>(NB, N);
    k_s3<<<NB, 256>>>(N);
    k_scatter<<<(E + 255) / 256, 256>>>(dst, E);

    int np_blocks = (N + 7) / 8;
    k_nodepass<<<np_blocks, 256>>>(ef, N);

    int nTiles = (N + TILE_N - 1) / TILE_N;
    int gemm_blocks = nTiles < 148 ? nTiles : 148;
    k_gemm<<<gemm_blocks, 256, SMEM_TOTAL>>>(h_in, W, out, N);
}